// round 10
// baseline (speedup 1.0000x reference)
#include <cuda_runtime.h>
#include <cuda_bf16.h>

// Fused DCNv2 forward, 2 pixels/thread, packed f32x2 math, constant weights,
// and a ZERO-PADDED NHWC4 re-layout of x ((H+2)x(W+2) float4) so that:
//   - conv window loads are unguarded LDG.128
//   - bilinear corners are clamp-to-border (IMNMX) instead of SETP/SEL guards

#define HH 512
#define WW 512
#define CC 3
#define OCC 27
#define KK 9
#define HW (HH * WW)
#define PW (WW + 2)              // padded width  514
#define PH (HH + 2)              // padded height 514
#define PIMG (PW * PH)           // 264196 padded px per image

typedef unsigned long long u64;

struct WConst {
    u64   wd[OCC * 27];   // duplicated {w,w}, transposed: wd[g*27+oc], g=c*9+ky*3+kx
    u64   wdd[3 * 27];    // duplicated w_def [o*27 + c*9 + k]
    float boff[28];
    float bdef[4];
};

__constant__ WConst c_w;
__device__   WConst g_scratch;

// zero-padded NHWC4 copy of x: g_xpad[b*PIMG + (y+1)*PW + (x+1)] = {c0,c1,c2,0}
__device__ __align__(16) float4 g_xpad[8 * PIMG];

__device__ __forceinline__ u64 pk2(float lo, float hi) {
    u64 r; asm("mov.b64 %0, {%1, %2};" : "=l"(r) : "f"(lo), "f"(hi)); return r;
}
__device__ __forceinline__ void upk2(u64 v, float& lo, float& hi) {
    asm("mov.b64 {%0, %1}, %2;" : "=f"(lo), "=f"(hi) : "l"(v));
}
__device__ __forceinline__ void ffma2(u64& acc, u64 a, u64 b) {
    asm("fma.rn.f32x2 %0, %1, %2, %0;" : "+l"(acc) : "l"(a), "l"(b));
}
__device__ __forceinline__ float f4c(const float4& q, int c) {
    return (c == 0) ? q.x : (c == 1) ? q.y : q.z;
}

// One kernel: blockIdx.y < 8 -> NHWC4 transform of image blockIdx.y;
//             blockIdx.y == 8 -> weight/bias prep (first 4 x-blocks).
__global__ __launch_bounds__(256)
void dcn_pre_kernel(const float* __restrict__ x,
                    const float* __restrict__ w_off,
                    const float* __restrict__ b_off,
                    const float* __restrict__ w_def,
                    const float* __restrict__ b_def)
{
    const int b = blockIdx.y;
    if (b < 8) {
        const int p = blockIdx.x * blockDim.x + threadIdx.x;
        if (p >= PIMG) return;
        const int yp = p / PW;          // 0..513
        const int xp = p - yp * PW;     // 0..513
        const int y = yp - 1, xx = xp - 1;
        float4 v = make_float4(0.0f, 0.0f, 0.0f, 0.0f);
        if ((unsigned)y < (unsigned)HH && (unsigned)xx < (unsigned)WW) {
            const float* xb = x + (size_t)b * CC * HW + y * WW + xx;
            v = make_float4(__ldg(xb), __ldg(xb + HW), __ldg(xb + 2 * HW), 0.0f);
        }
        g_xpad[(size_t)b * PIMG + p] = v;
        return;
    }
    // weight prep (needs 896 threads = first 4 x-blocks)
    if (blockIdx.x >= 4) return;
    const int i = blockIdx.x * 256 + threadIdx.x;
    if (i < OCC * 27) {
        const int g = i / OCC, oc = i % OCC;
        const float w = w_off[oc * 27 + g];
        g_scratch.wd[g * 27 + oc] = pk2(w, w);
    } else if (i < OCC * 27 + 81) {
        const int j = i - OCC * 27;
        g_scratch.wdd[j] = pk2(w_def[j], w_def[j]);
    } else if (i < OCC * 27 + 81 + 28) {
        const int j = i - (OCC * 27 + 81);
        g_scratch.boff[j] = (j < OCC) ? b_off[j] : 0.0f;
    } else if (i < OCC * 27 + 81 + 32) {
        const int j = i - (OCC * 27 + 81 + 28);
        g_scratch.bdef[j] = (j < 3) ? b_def[j] : 0.0f;
    }
}

__global__ __launch_bounds__(128, 5)
void dcn_fused_pad(float* __restrict__ out)
{
    // One thread = pixel pair (hI, wI), (hI, wI+1) with wI even.
    const int idx = blockIdx.x * blockDim.x + threadIdx.x;   // 0 .. 8*512*256-1
    const int wI = (idx & 255) << 1;
    const int hI = (idx >> 8) & (HH - 1);
    const int b  = idx >> 17;

    const float4* xp = g_xpad + (size_t)b * PIMG;   // padded, origin at (-1,-1)

    // ---- offset/mask conv, row-streamed, UNGUARDED loads ----
    u64 ow[OCC];
#pragma unroll
    for (int oc = 0; oc < OCC; ++oc) {
        const float bv = c_w.boff[oc];
        ow[oc] = pk2(bv, bv);
    }

#pragma unroll
    for (int r = 0; r < 3; ++r) {
        const float4* rowp = xp + (hI + r) * PW + wI;   // padded row hI+r-1
        float4 row[4];
#pragma unroll
        for (int j = 0; j < 4; ++j) row[j] = __ldg(rowp + j);
#pragma unroll
        for (int kx = 0; kx < 3; ++kx) {
#pragma unroll
            for (int c = 0; c < CC; ++c) {
                const u64 v2 = pk2(f4c(row[kx], c), f4c(row[kx + 1], c));
                const int gbase = (c * 9 + r * 3 + kx) * 27;   // compile-time
#pragma unroll
                for (int oc = 0; oc < OCC; ++oc)
                    ffma2(ow[oc], c_w.wd[gbase + oc], v2);
            }
        }
    }

    // ---- deformable sampling + channel mix (packed across the 2 pixels) ----
    u64 acc[3];
#pragma unroll
    for (int o = 0; o < 3; ++o) {
        const float bv = c_w.bdef[o];
        acc[o] = pk2(bv, bv);
    }

#pragma unroll
    for (int k = 0; k < KK; ++k) {
        float oy0, oy1, ox0, ox1, z0, z1;
        upk2(ow[2 * k],     oy0, oy1);
        upk2(ow[2 * k + 1], ox0, ox1);
        upk2(ow[18 + k],    z0,  z1);
        const float m0 = __fdividef(1.0f, 1.0f + __expf(-z0));
        const float m1 = __fdividef(1.0f, 1.0f + __expf(-z1));

        const float kyf = (float)(k / 3 - 1);
        const float kxf = (float)(k % 3 - 1);

        float val[2][CC];
#pragma unroll
        for (int p = 0; p < 2; ++p) {
            const float py = (float)hI + kyf + (p ? oy1 : oy0);
            const float px = (float)(wI + p) + kxf + (p ? ox1 : ox0);
            const float y0f = floorf(py);
            const float x0f = floorf(px);
            const float dy = py - y0f;
            const float dx = px - x0f;
            const int y0 = (int)y0f;
            const int x0 = (int)x0f;

            const float w00 = (1.0f - dy) * (1.0f - dx);
            const float w01 = (1.0f - dy) * dx;
            const float w10 = dy * (1.0f - dx);
            const float w11 = dy * dx;

            // clamp-to-border: padded array is zero on [-1,H]x[-1,W] border,
            // and any coordinate outside clamps onto that zero border.
            const int yc0 = min(max(y0,     -1), HH);
            const int yc1 = min(max(y0 + 1, -1), HH);
            const int xc0 = min(max(x0,     -1), WW);
            const int xc1 = min(max(x0 + 1, -1), WW);

            const float4* r0 = xp + (yc0 + 1) * PW;
            const float4* r1 = xp + (yc1 + 1) * PW;
            const float4 q00 = __ldg(r0 + xc0 + 1);
            const float4 q01 = __ldg(r0 + xc1 + 1);
            const float4 q10 = __ldg(r1 + xc0 + 1);
            const float4 q11 = __ldg(r1 + xc1 + 1);

#pragma unroll
            for (int c = 0; c < CC; ++c)
                val[p][c] = f4c(q00, c) * w00 + f4c(q01, c) * w01
                          + f4c(q10, c) * w10 + f4c(q11, c) * w11;
        }

#pragma unroll
        for (int c = 0; c < CC; ++c) {
            const u64 vp = pk2(val[0][c] * m0, val[1][c] * m1);
#pragma unroll
            for (int o = 0; o < 3; ++o)
                ffma2(acc[o], c_w.wdd[o * 27 + c * 9 + k], vp);
        }
    }

    const size_t obase = (size_t)b * 3 * HW + (size_t)hI * WW + wI;
#pragma unroll
    for (int o = 0; o < 3; ++o) {
        float lo, hi; upk2(acc[o], lo, hi);
        *reinterpret_cast<float2*>(out + obase + (size_t)o * HW) = make_float2(lo, hi);
    }
}

extern "C" void kernel_launch(void* const* d_in, const int* in_sizes, int n_in,
                              void* d_out, int out_size)
{
    const float* x     = (const float*)d_in[0];
    const float* w_off = (const float*)d_in[1];
    const float* b_off = (const float*)d_in[2];
    const float* w_def = (const float*)d_in[3];
    const float* b_def = (const float*)d_in[4];
    float* out = (float*)d_out;

    // 1) Transform x -> padded NHWC4 + build weight blob (one kernel).
    {
        dim3 grid((PIMG + 255) / 256, 9);
        dcn_pre_kernel<<<grid, 256>>>(x, w_off, b_off, w_def, b_def);
    }

    // 2) Stage weight blob into __constant__ (one D2D copy).
    void* scratch_ptr = nullptr;
    cudaGetSymbolAddress(&scratch_ptr, g_scratch);
    cudaMemcpyToSymbolAsync(c_w, scratch_ptr, sizeof(WConst), 0,
                            cudaMemcpyDeviceToDevice);

    // 3) Main fused kernel.
    const int totalPairs = 8 * 512 * 256;    // 1,048,576 pixel pairs
    dcn_fused_pad<<<totalPairs / 128, 128>>>(out);
}

// round 11
// speedup vs baseline: 1.0630x; 1.0630x over previous
#include <cuda_runtime.h>
#include <cuda_bf16.h>

// Fused DCNv2 forward, 2 pixels/thread, packed f32x2 conv math, constant
// weights (uniform LDCU), and a ZERO-PADDED per-channel SCALAR layout of x
// (B, 3, 514, 516) so conv-window loads are unguarded and bilinear corners
// are clamp-to-(zero)-border IMNMX instead of SETP/SEL guards.
// Scattered reads stay LDG.32 (R10 showed float4 gathers blow up L1 wavefronts).

#define HH 512
#define WW 512
#define CC 3
#define OCC 27
#define KK 9
#define HW (HH * WW)
#define PH2 514            // padded rows: y in [-1, 512]
#define PW2 516            // padded cols: x in [-2, 513] (516 keeps 8B alignment)
#define PIMG (PH2 * PW2)   // 265224

typedef unsigned long long u64;

struct WConst {
    u64   wd[OCC * 27];   // duplicated {w,w}, transposed: wd[g*27+oc], g=c*9+ky*3+kx
    u64   wdd[3 * 27];    // duplicated w_def [o*27 + c*9 + k]
    float boff[28];
    float bdef[4];
};

__constant__ WConst c_w;
__device__   WConst g_scratch;

// padded scalar copy: g_xpad[(b*3+c)*PIMG + (y+1)*PW2 + (x+2)] ; zero outside image
__device__ __align__(16) float g_xpad[8 * CC * PIMG];

__device__ __forceinline__ u64 pk2(float lo, float hi) {
    u64 r; asm("mov.b64 %0, {%1, %2};" : "=l"(r) : "f"(lo), "f"(hi)); return r;
}
__device__ __forceinline__ void upk2(u64 v, float& lo, float& hi) {
    asm("mov.b64 {%0, %1}, %2;" : "=f"(lo), "=f"(hi) : "l"(v));
}
__device__ __forceinline__ void ffma2(u64& acc, u64 a, u64 b) {
    asm("fma.rn.f32x2 %0, %1, %2, %0;" : "+l"(acc) : "l"(a), "l"(b));
}

// blockIdx.y < 24: pad-transform channel (b*3+c) = blockIdx.y.
// blockIdx.y == 24: weight/bias prep (first 4 x-blocks).
__global__ __launch_bounds__(256)
void dcn_pre_kernel(const float* __restrict__ x,
                    const float* __restrict__ w_off,
                    const float* __restrict__ b_off,
                    const float* __restrict__ w_def,
                    const float* __restrict__ b_def)
{
    const int ch = blockIdx.y;
    if (ch < 24) {
        const int p = blockIdx.x * blockDim.x + threadIdx.x;
        if (p >= PIMG) return;
        const int yp = p / PW2;
        const int xp = p - yp * PW2;
        const int y = yp - 1, xx = xp - 2;
        float v = 0.0f;
        if ((unsigned)y < (unsigned)HH && (unsigned)xx < (unsigned)WW)
            v = __ldg(x + (size_t)ch * HW + y * WW + xx);
        g_xpad[(size_t)ch * PIMG + p] = v;
        return;
    }
    if (blockIdx.x >= 4) return;
    const int i = blockIdx.x * 256 + threadIdx.x;
    if (i < OCC * 27) {
        const int g = i / OCC, oc = i % OCC;
        const float w = w_off[oc * 27 + g];
        g_scratch.wd[g * 27 + oc] = pk2(w, w);
    } else if (i < OCC * 27 + 81) {
        const int j = i - OCC * 27;
        g_scratch.wdd[j] = pk2(w_def[j], w_def[j]);
    } else if (i < OCC * 27 + 81 + 28) {
        const int j = i - (OCC * 27 + 81);
        g_scratch.boff[j] = (j < OCC) ? b_off[j] : 0.0f;
    } else if (i < OCC * 27 + 81 + 32) {
        const int j = i - (OCC * 27 + 81 + 28);
        g_scratch.bdef[j] = (j < 3) ? b_def[j] : 0.0f;
    }
}

__global__ __launch_bounds__(128, 5)
void dcn_fused_pad(float* __restrict__ out)
{
    // One thread = pixel pair (hI, wI), (hI, wI+1) with wI even.
    const int idx = blockIdx.x * blockDim.x + threadIdx.x;   // 0 .. 8*512*256-1
    const int wI = (idx & 255) << 1;
    const int hI = (idx >> 8) & (HH - 1);
    const int b  = idx >> 17;

    const float* xpb = g_xpad + (size_t)b * CC * PIMG;

    // ---- offset/mask conv on both pixels (packed), UNGUARDED window loads ----
    u64 ow[OCC];
#pragma unroll
    for (int oc = 0; oc < OCC; ++oc) {
        const float bv = c_w.boff[oc];
        ow[oc] = pk2(bv, bv);
    }

#pragma unroll
    for (int c = 0; c < CC; ++c) {
        const float* pc = xpb + c * PIMG;
        float win[12];   // 3 rows x 4 cols (x = wI-1 .. wI+2)
#pragma unroll
        for (int r = 0; r < 3; ++r) {
            // padded row index = hI + r ; padded col for x=wI+j-1 is wI+j+1
            const float* rowp = pc + (hI + r) * PW2 + wI;
            const float2 mid = __ldg(reinterpret_cast<const float2*>(rowp + 2));
            win[r * 4 + 0] = __ldg(rowp + 1);
            win[r * 4 + 1] = mid.x;
            win[r * 4 + 2] = mid.y;
            win[r * 4 + 3] = __ldg(rowp + 4);
        }
#pragma unroll
        for (int t = 0; t < 9; ++t) {
            const int ky = t / 3, kx = t % 3;
            const u64 v2 = pk2(win[ky * 4 + kx], win[ky * 4 + kx + 1]);
            const int gbase = (c * 9 + t) * 27;   // compile-time after unroll
#pragma unroll
            for (int oc = 0; oc < OCC; ++oc)
                ffma2(ow[oc], c_w.wd[gbase + oc], v2);
        }
    }

    // ---- deformable sampling + channel mix (packed across the 2 pixels) ----
    u64 acc[3];
#pragma unroll
    for (int o = 0; o < 3; ++o) {
        const float bv = c_w.bdef[o];
        acc[o] = pk2(bv, bv);
    }

#pragma unroll
    for (int k = 0; k < KK; ++k) {
        float oy0, oy1, ox0, ox1, z0, z1;
        upk2(ow[2 * k],     oy0, oy1);
        upk2(ow[2 * k + 1], ox0, ox1);
        upk2(ow[18 + k],    z0,  z1);
        const float m0 = __fdividef(1.0f, 1.0f + __expf(-z0));
        const float m1 = __fdividef(1.0f, 1.0f + __expf(-z1));

        const float kyf = (float)(k / 3 - 1);
        const float kxf = (float)(k % 3 - 1);

        float w00[2], w01[2], w10[2], w11[2];
        int   a00[2], a01[2], a10[2], a11[2];
#pragma unroll
        for (int p = 0; p < 2; ++p) {
            const float py = (float)hI + kyf + (p ? oy1 : oy0);
            const float px = (float)(wI + p) + kxf + (p ? ox1 : ox0);
            const float y0f = floorf(py);
            const float x0f = floorf(px);
            const float dy = py - y0f;
            const float dx = px - x0f;
            const int y0 = (int)y0f;
            const int x0 = (int)x0f;

            w00[p] = (1.0f - dy) * (1.0f - dx);
            w01[p] = (1.0f - dy) * dx;
            w10[p] = dy * (1.0f - dx);
            w11[p] = dy * dx;

            // clamp-to-zero-border: coords outside [-1,512] land on zero cells
            const int yc0 = min(max(y0,     -1), HH);
            const int yc1 = min(max(y0 + 1, -1), HH);
            const int xc0 = min(max(x0,     -1), WW);
            const int xc1 = min(max(x0 + 1, -1), WW);
            const int r0 = (yc0 + 1) * PW2;
            const int r1 = (yc1 + 1) * PW2;
            a00[p] = r0 + xc0 + 2;
            a01[p] = r0 + xc1 + 2;
            a10[p] = r1 + xc0 + 2;
            a11[p] = r1 + xc1 + 2;
        }

#pragma unroll
        for (int c = 0; c < CC; ++c) {
            const float* pc = xpb + c * PIMG;
            float val[2];
#pragma unroll
            for (int p = 0; p < 2; ++p) {
                const float v00 = __ldg(pc + a00[p]);
                const float v01 = __ldg(pc + a01[p]);
                const float v10 = __ldg(pc + a10[p]);
                const float v11 = __ldg(pc + a11[p]);
                val[p] = v00 * w00[p] + v01 * w01[p] + v10 * w10[p] + v11 * w11[p];
            }
            const u64 vp = pk2(val[0] * m0, val[1] * m1);
#pragma unroll
            for (int o = 0; o < 3; ++o)
                ffma2(acc[o], c_w.wdd[o * 27 + c * 9 + k], vp);
        }
    }

    const size_t obase = (size_t)b * 3 * HW + (size_t)hI * WW + wI;
#pragma unroll
    for (int o = 0; o < 3; ++o) {
        float lo, hi; upk2(acc[o], lo, hi);
        *reinterpret_cast<float2*>(out + obase + (size_t)o * HW) = make_float2(lo, hi);
    }
}

extern "C" void kernel_launch(void* const* d_in, const int* in_sizes, int n_in,
                              void* d_out, int out_size)
{
    const float* x     = (const float*)d_in[0];
    const float* w_off = (const float*)d_in[1];
    const float* b_off = (const float*)d_in[2];
    const float* w_def = (const float*)d_in[3];
    const float* b_def = (const float*)d_in[4];
    float* out = (float*)d_out;

    // 1) Padded scalar transform + weight prep (one kernel).
    {
        dim3 grid((PIMG + 255) / 256, 25);
        dcn_pre_kernel<<<grid, 256>>>(x, w_off, b_off, w_def, b_def);
    }

    // 2) Stage weight blob into __constant__ (one D2D copy).
    void* scratch_ptr = nullptr;
    cudaGetSymbolAddress(&scratch_ptr, g_scratch);
    cudaMemcpyToSymbolAsync(c_w, scratch_ptr, sizeof(WConst), 0,
                            cudaMemcpyDeviceToDevice);

    // 3) Main fused kernel.
    const int totalPairs = 8 * 512 * 256;    // 1,048,576 pixel pairs
    dcn_fused_pad<<<totalPairs / 128, 128>>>(out);
}

// round 12
// speedup vs baseline: 1.1763x; 1.1067x over previous
#include <cuda_runtime.h>
#include <cuda_bf16.h>

// Fused DCNv2 forward, 1 pixel/thread, conv accumulators packed over CHANNEL
// pairs ({y,x} offsets, mask pairs) with f32x2 FMAs. Weights prepacked per
// window-position g into 128B constant rows (7 x LDCU.128 per g). No x
// re-layout pre-pass (R11 showed it's a wash + 15us overhead).

#define HH 512
#define WW 512
#define CC 3
#define OCC 27
#define KK 9
#define HW (HH * WW)

typedef unsigned long long u64;

// Per-g constant row (16 u64 = 128B):
//   j = 0..8 : {w_off[2k][g],   w_off[2k+1][g]}   (k = j)      offset pairs
//   j = 9..13: {w_off[18+2m][g], w_off[19+2m][g]} (m = j-9; m=4 hi = 0) masks
//   j = 14,15: zero pad
struct GBlob {
    u64   cG[27 * 16];    // 3456 B
    float wdd[84];        // w_def [o*27 + c*9 + k], padded
    float boff[28];
    float bdef[4];
};

__constant__ GBlob c_b;
__device__   GBlob g_scratch;

__device__ __forceinline__ u64 pk2(float lo, float hi) {
    u64 r; asm("mov.b64 %0, {%1, %2};" : "=l"(r) : "f"(lo), "f"(hi)); return r;
}
__device__ __forceinline__ void upk2(u64 v, float& lo, float& hi) {
    asm("mov.b64 {%0, %1}, %2;" : "=f"(lo), "=f"(hi) : "l"(v));
}
__device__ __forceinline__ void ffma2(u64& acc, u64 a, u64 b) {
    asm("fma.rn.f32x2 %0, %1, %2, %0;" : "+l"(acc) : "l"(a), "l"(b));
}

__global__ void dcn_prep_kernel(const float* __restrict__ w_off,
                                const float* __restrict__ b_off,
                                const float* __restrict__ w_def,
                                const float* __restrict__ b_def)
{
    const int i = threadIdx.x;
    if (i < 27 * 16) {                 // cG entries
        const int g = i >> 4, j = i & 15;
        u64 v = 0ull;
        if (j < 9) {
            v = pk2(w_off[(2 * j) * 27 + g], w_off[(2 * j + 1) * 27 + g]);
        } else if (j < 14) {
            const int m = j - 9;
            const float hi = (m < 4) ? w_off[(19 + 2 * m) * 27 + g] : 0.0f;
            v = pk2(w_off[(18 + 2 * m) * 27 + g], hi);
        }
        g_scratch.cG[i] = v;
    } else if (i < 432 + 84) {
        const int j = i - 432;
        g_scratch.wdd[j] = (j < 81) ? w_def[j] : 0.0f;
    } else if (i < 432 + 84 + 28) {
        const int j = i - 516;
        g_scratch.boff[j] = (j < OCC) ? b_off[j] : 0.0f;
    } else if (i < 432 + 84 + 32) {
        const int j = i - 544;
        g_scratch.bdef[j] = (j < 3) ? b_def[j] : 0.0f;
    }
}

__global__ __launch_bounds__(128, 6)
void dcn_fused1_kernel(const float* __restrict__ x, float* __restrict__ out)
{
    const int idx = blockIdx.x * blockDim.x + threadIdx.x;   // pixel id
    const int wI = idx & (WW - 1);
    const int hI = (idx >> 9) & (HH - 1);
    const int b  = idx >> 18;

    const float* xb = x + (size_t)b * CC * HW;

    // ---- 3x3x3 window (zero padded), win[g], g = c*9 + ky*3 + kx ----
    float win[27];
#pragma unroll
    for (int c = 0; c < CC; ++c) {
        const float* xc = xb + c * HW;
#pragma unroll
        for (int ky = 0; ky < 3; ++ky) {
            const int y = hI + ky - 1;
            const bool yv = ((unsigned)y < (unsigned)HH);
#pragma unroll
            for (int kx = 0; kx < 3; ++kx) {
                const int xx = wI + kx - 1;
                const bool v = yv && ((unsigned)xx < (unsigned)WW);
                win[c * 9 + ky * 3 + kx] = v ? __ldg(xc + y * WW + xx) : 0.0f;
            }
        }
    }

    // ---- conv, channel-packed accumulators ----
    u64 oyx[9];   // {ow_y_k, ow_x_k}
    u64 om[5];    // {mask_2m, mask_2m+1} (om[4] hi unused/0)
#pragma unroll
    for (int k = 0; k < 9; ++k) oyx[k] = pk2(c_b.boff[2 * k], c_b.boff[2 * k + 1]);
#pragma unroll
    for (int m = 0; m < 5; ++m)
        om[m] = pk2(c_b.boff[18 + 2 * m], (m < 4) ? c_b.boff[19 + 2 * m] : 0.0f);

#pragma unroll
    for (int g = 0; g < 27; ++g) {
        const u64 vd = pk2(win[g], win[g]);
#pragma unroll
        for (int k = 0; k < 9; ++k) ffma2(oyx[k], c_b.cG[g * 16 + k], vd);
#pragma unroll
        for (int m = 0; m < 5; ++m) ffma2(om[m], c_b.cG[g * 16 + 9 + m], vd);
    }

    // mask logits
    float mz[10];
#pragma unroll
    for (int m = 0; m < 5; ++m) upk2(om[m], mz[2 * m], mz[2 * m + 1]);

    // ---- deformable sampling + 3-channel mix ----
    float acc0 = c_b.bdef[0], acc1 = c_b.bdef[1], acc2 = c_b.bdef[2];

#pragma unroll
    for (int k = 0; k < KK; ++k) {
        float oy, ox;
        upk2(oyx[k], oy, ox);
        const float py = (float)hI + (float)(k / 3 - 1) + oy;
        const float px = (float)wI + (float)(k % 3 - 1) + ox;
        const float m  = __fdividef(1.0f, 1.0f + __expf(-mz[k]));

        const float y0f = floorf(py);
        const float x0f = floorf(px);
        const float dy = py - y0f;
        const float dx = px - x0f;
        const int y0  = (int)y0f;
        const int x0i = (int)x0f;

        const float w00 = (1.0f - dy) * (1.0f - dx) * m;
        const float w01 = (1.0f - dy) * dx * m;
        const float w10 = dy * (1.0f - dx) * m;
        const float w11 = dy * dx * m;

        const bool y0v = ((unsigned)y0        < (unsigned)HH);
        const bool y1v = ((unsigned)(y0 + 1)  < (unsigned)HH);
        const bool x0v = ((unsigned)x0i       < (unsigned)WW);
        const bool x1v = ((unsigned)(x0i + 1) < (unsigned)WW);
        const int i00 = y0 * WW + x0i;

#pragma unroll
        for (int c = 0; c < CC; ++c) {
            const float* pc = xb + c * HW;
            const float v00 = (y0v && x0v) ? __ldg(pc + i00)          : 0.0f;
            const float v01 = (y0v && x1v) ? __ldg(pc + i00 + 1)      : 0.0f;
            const float v10 = (y1v && x0v) ? __ldg(pc + i00 + WW)     : 0.0f;
            const float v11 = (y1v && x1v) ? __ldg(pc + i00 + WW + 1) : 0.0f;

            const float val = v00 * w00 + v01 * w01 + v10 * w10 + v11 * w11;

            acc0 = fmaf(c_b.wdd[0 * 27 + c * 9 + k], val, acc0);
            acc1 = fmaf(c_b.wdd[1 * 27 + c * 9 + k], val, acc1);
            acc2 = fmaf(c_b.wdd[2 * 27 + c * 9 + k], val, acc2);
        }
    }

    const size_t obase = (size_t)b * 3 * HW + (size_t)hI * WW + wI;
    out[obase]          = acc0;
    out[obase + HW]     = acc1;
    out[obase + 2 * HW] = acc2;
}

extern "C" void kernel_launch(void* const* d_in, const int* in_sizes, int n_in,
                              void* d_out, int out_size)
{
    const float* x     = (const float*)d_in[0];
    const float* w_off = (const float*)d_in[1];
    const float* b_off = (const float*)d_in[2];
    const float* w_def = (const float*)d_in[3];
    const float* b_def = (const float*)d_in[4];
    float* out = (float*)d_out;

    // 1) Build packed weight blob in device scratch.
    dcn_prep_kernel<<<1, 576>>>(w_off, b_off, w_def, b_def);

    // 2) Stage blob into __constant__ (one D2D copy).
    void* scratch_ptr = nullptr;
    cudaGetSymbolAddress(&scratch_ptr, g_scratch);
    cudaMemcpyToSymbolAsync(c_b, scratch_ptr, sizeof(GBlob), 0,
                            cudaMemcpyDeviceToDevice);

    // 3) Main fused kernel: 1 px/thread.
    const int totalPx = 8 * HW;              // 2,097,152
    dcn_fused1_kernel<<<totalPx / 128, 128>>>(x, out);
}

// round 13
// speedup vs baseline: 1.4348x; 1.2197x over previous
#include <cuda_runtime.h>
#include <cuda_bf16.h>

// Fused DCNv2 forward, 1 pixel/thread, channel-packed f32x2 conv accumulators,
// constant-memory packed weights, and a data-dependent INTERIOR FAST PATH in
// the deformable sampling loop (unguarded corner loads when all 4 corners are
// in-bounds, which holds for >99% of samples; exact guarded fallback otherwise).

#define HH 512
#define WW 512
#define CC 3
#define OCC 27
#define KK 9
#define HW (HH * WW)

typedef unsigned long long u64;

// Per-g constant row (16 u64 = 128B):
//   j = 0..8 : {w_off[2k][g],   w_off[2k+1][g]}   (k = j)      offset pairs
//   j = 9..13: {w_off[18+2m][g], w_off[19+2m][g]} (m = j-9; m=4 hi = 0) masks
struct GBlob {
    u64   cG[27 * 16];
    float wdd[84];        // w_def [o*27 + c*9 + k]
    float boff[28];
    float bdef[4];
};

__constant__ GBlob c_b;
__device__   GBlob g_scratch;

__device__ __forceinline__ u64 pk2(float lo, float hi) {
    u64 r; asm("mov.b64 %0, {%1, %2};" : "=l"(r) : "f"(lo), "f"(hi)); return r;
}
__device__ __forceinline__ void upk2(u64 v, float& lo, float& hi) {
    asm("mov.b64 {%0, %1}, %2;" : "=f"(lo), "=f"(hi) : "l"(v));
}
__device__ __forceinline__ void ffma2(u64& acc, u64 a, u64 b) {
    asm("fma.rn.f32x2 %0, %1, %2, %0;" : "+l"(acc) : "l"(a), "l"(b));
}

__global__ void dcn_prep_kernel(const float* __restrict__ w_off,
                                const float* __restrict__ b_off,
                                const float* __restrict__ w_def,
                                const float* __restrict__ b_def)
{
    const int i = threadIdx.x;
    if (i < 27 * 16) {
        const int g = i >> 4, j = i & 15;
        u64 v = 0ull;
        if (j < 9) {
            v = pk2(w_off[(2 * j) * 27 + g], w_off[(2 * j + 1) * 27 + g]);
        } else if (j < 14) {
            const int m = j - 9;
            const float hi = (m < 4) ? w_off[(19 + 2 * m) * 27 + g] : 0.0f;
            v = pk2(w_off[(18 + 2 * m) * 27 + g], hi);
        }
        g_scratch.cG[i] = v;
    } else if (i < 432 + 84) {
        const int j = i - 432;
        g_scratch.wdd[j] = (j < 81) ? w_def[j] : 0.0f;
    } else if (i < 432 + 84 + 28) {
        const int j = i - 516;
        g_scratch.boff[j] = (j < OCC) ? b_off[j] : 0.0f;
    } else if (i < 432 + 84 + 32) {
        const int j = i - 544;
        g_scratch.bdef[j] = (j < 3) ? b_def[j] : 0.0f;
    }
}

__global__ __launch_bounds__(128, 6)
void dcn_fused1_kernel(const float* __restrict__ x, float* __restrict__ out)
{
    const int idx = blockIdx.x * blockDim.x + threadIdx.x;   // pixel id
    const int wI = idx & (WW - 1);
    const int hI = (idx >> 9) & (HH - 1);
    const int b  = idx >> 18;

    const float* xb = x + (size_t)b * CC * HW;

    // ---- 3x3x3 window (zero padded), win[g], g = c*9 + ky*3 + kx ----
    float win[27];
#pragma unroll
    for (int c = 0; c < CC; ++c) {
        const float* xc = xb + c * HW;
#pragma unroll
        for (int ky = 0; ky < 3; ++ky) {
            const int y = hI + ky - 1;
            const bool yv = ((unsigned)y < (unsigned)HH);
#pragma unroll
            for (int kx = 0; kx < 3; ++kx) {
                const int xx = wI + kx - 1;
                const bool v = yv && ((unsigned)xx < (unsigned)WW);
                win[c * 9 + ky * 3 + kx] = v ? __ldg(xc + y * WW + xx) : 0.0f;
            }
        }
    }

    // ---- conv, channel-packed accumulators ----
    u64 oyx[9];   // {ow_y_k, ow_x_k}
    u64 om[5];    // {mask_2m, mask_2m+1}
#pragma unroll
    for (int k = 0; k < 9; ++k) oyx[k] = pk2(c_b.boff[2 * k], c_b.boff[2 * k + 1]);
#pragma unroll
    for (int m = 0; m < 5; ++m)
        om[m] = pk2(c_b.boff[18 + 2 * m], (m < 4) ? c_b.boff[19 + 2 * m] : 0.0f);

#pragma unroll
    for (int g = 0; g < 27; ++g) {
        const u64 vd = pk2(win[g], win[g]);
#pragma unroll
        for (int k = 0; k < 9; ++k) ffma2(oyx[k], c_b.cG[g * 16 + k], vd);
#pragma unroll
        for (int m = 0; m < 5; ++m) ffma2(om[m], c_b.cG[g * 16 + 9 + m], vd);
    }

    float mz[10];
#pragma unroll
    for (int m = 0; m < 5; ++m) upk2(om[m], mz[2 * m], mz[2 * m + 1]);

    // ---- deformable sampling + 3-channel mix ----
    float acc0 = c_b.bdef[0], acc1 = c_b.bdef[1], acc2 = c_b.bdef[2];

#pragma unroll
    for (int k = 0; k < KK; ++k) {
        float oy, ox;
        upk2(oyx[k], oy, ox);
        const float py = (float)hI + (float)(k / 3 - 1) + oy;
        const float px = (float)wI + (float)(k % 3 - 1) + ox;
        const float m  = __fdividef(1.0f, 1.0f + __expf(-mz[k]));

        const float y0f = floorf(py);
        const float x0f = floorf(px);
        const float dy = py - y0f;
        const float dx = px - x0f;
        const int y0  = (int)y0f;
        const int x0i = (int)x0f;

        const float a  = (1.0f - dy) * m;
        const float bm = dy * m;
        const float w00 = a  * (1.0f - dx);
        const float w01 = a  * dx;
        const float w10 = bm * (1.0f - dx);
        const float w11 = bm * dx;

        const int i00 = y0 * WW + x0i;

        if ((unsigned)y0 < (unsigned)(HH - 1) && (unsigned)x0i < (unsigned)(WW - 1)) {
            // FAST PATH: all four corners in-bounds -> unguarded loads
#pragma unroll
            for (int c = 0; c < CC; ++c) {
                const float* pc = xb + c * HW;
                const float v00 = __ldg(pc + i00);
                const float v01 = __ldg(pc + i00 + 1);
                const float v10 = __ldg(pc + i00 + WW);
                const float v11 = __ldg(pc + i00 + WW + 1);
                const float val = v00 * w00 + v01 * w01 + v10 * w10 + v11 * w11;
                acc0 = fmaf(c_b.wdd[0 * 27 + c * 9 + k], val, acc0);
                acc1 = fmaf(c_b.wdd[1 * 27 + c * 9 + k], val, acc1);
                acc2 = fmaf(c_b.wdd[2 * 27 + c * 9 + k], val, acc2);
            }
        } else {
            // SLOW PATH: exact guarded sampling (borders / large offsets)
            const bool y0v = ((unsigned)y0        < (unsigned)HH);
            const bool y1v = ((unsigned)(y0 + 1)  < (unsigned)HH);
            const bool x0v = ((unsigned)x0i       < (unsigned)WW);
            const bool x1v = ((unsigned)(x0i + 1) < (unsigned)WW);
#pragma unroll
            for (int c = 0; c < CC; ++c) {
                const float* pc = xb + c * HW;
                const float v00 = (y0v && x0v) ? __ldg(pc + i00)          : 0.0f;
                const float v01 = (y0v && x1v) ? __ldg(pc + i00 + 1)      : 0.0f;
                const float v10 = (y1v && x0v) ? __ldg(pc + i00 + WW)     : 0.0f;
                const float v11 = (y1v && x1v) ? __ldg(pc + i00 + WW + 1) : 0.0f;
                const float val = v00 * w00 + v01 * w01 + v10 * w10 + v11 * w11;
                acc0 = fmaf(c_b.wdd[0 * 27 + c * 9 + k], val, acc0);
                acc1 = fmaf(c_b.wdd[1 * 27 + c * 9 + k], val, acc1);
                acc2 = fmaf(c_b.wdd[2 * 27 + c * 9 + k], val, acc2);
            }
        }
    }

    const size_t obase = (size_t)b * 3 * HW + (size_t)hI * WW + wI;
    out[obase]          = acc0;
    out[obase + HW]     = acc1;
    out[obase + 2 * HW] = acc2;
}

extern "C" void kernel_launch(void* const* d_in, const int* in_sizes, int n_in,
                              void* d_out, int out_size)
{
    const float* x     = (const float*)d_in[0];
    const float* w_off = (const float*)d_in[1];
    const float* b_off = (const float*)d_in[2];
    const float* w_def = (const float*)d_in[3];
    const float* b_def = (const float*)d_in[4];
    float* out = (float*)d_out;

    // 1) Build packed weight blob in device scratch.
    dcn_prep_kernel<<<1, 576>>>(w_off, b_off, w_def, b_def);

    // 2) Stage blob into __constant__ (one D2D copy).
    void* scratch_ptr = nullptr;
    cudaGetSymbolAddress(&scratch_ptr, g_scratch);
    cudaMemcpyToSymbolAsync(c_b, scratch_ptr, sizeof(GBlob), 0,
                            cudaMemcpyDeviceToDevice);

    // 3) Main fused kernel: 1 px/thread.
    const int totalPx = 8 * HW;              // 2,097,152
    dcn_fused1_kernel<<<totalPx / 128, 128>>>(x, out);
}